// round 1
// baseline (speedup 1.0000x reference)
#include <cuda_runtime.h>

// SpikesEncoder: out[t, i] = LIF spike train, input current = x @ W (W: [N, N] row-major).
// N = 8192 units, T = 256 steps. alpha = exp(-0.1), threshold = 1.0.

#define N_UNITS 8192
#define N_STEPS 256
#define KSPLITS 32
#define ROWS_PER_SPLIT (N_UNITS / KSPLITS)  // 256
#define JTILE 256

// Scratch for matvec partial sums: 32 * 8192 floats = 1 MB. Device global (no alloc).
__device__ float g_partial[KSPLITS * N_UNITS];

// Kernel 1: partial matvec. Block (jtile, ksplit): 256 threads each own one output
// column j, accumulate over 256 rows of W (coalesced 1 KB row segments).
__global__ void __launch_bounds__(JTILE) matvec_partial_kernel(
    const float* __restrict__ x, const float* __restrict__ W)
{
    __shared__ float xs[ROWS_PER_SPLIT];
    const int j  = blockIdx.x * JTILE + threadIdx.x;
    const int k0 = blockIdx.y * ROWS_PER_SPLIT;

    xs[threadIdx.x] = x[k0 + threadIdx.x];
    __syncthreads();

    const float* __restrict__ Wp = W + (size_t)k0 * N_UNITS + j;
    float acc0 = 0.0f, acc1 = 0.0f, acc2 = 0.0f, acc3 = 0.0f;
    #pragma unroll 4
    for (int kk = 0; kk < ROWS_PER_SPLIT; kk += 4) {
        acc0 = fmaf(xs[kk + 0], Wp[(size_t)(kk + 0) * N_UNITS], acc0);
        acc1 = fmaf(xs[kk + 1], Wp[(size_t)(kk + 1) * N_UNITS], acc1);
        acc2 = fmaf(xs[kk + 2], Wp[(size_t)(kk + 2) * N_UNITS], acc2);
        acc3 = fmaf(xs[kk + 3], Wp[(size_t)(kk + 3) * N_UNITS], acc3);
    }
    g_partial[blockIdx.y * N_UNITS + j] = (acc0 + acc1) + (acc2 + acc3);
}

// Kernel 2: reduce partials to input current, then run the 256-step LIF recurrence.
// Each thread owns one unit; stores at step t are coalesced across the warp.
__global__ void __launch_bounds__(256) lif_kernel(float* __restrict__ out)
{
    const int i = blockIdx.x * 256 + threadIdx.x;

    float I = 0.0f;
    #pragma unroll
    for (int s = 0; s < KSPLITS; s++)
        I += g_partial[s * N_UNITS + i];

    const float ALPHA = 0.9048374180359595f;  // exp(-0.1) rounded to f32
    float V = 0.0f, Z = 0.0f;

    float* __restrict__ op = out + i;
    #pragma unroll 8
    for (int t = 0; t < N_STEPS; t++) {
        V = fmaf(ALPHA, V, I) * (1.0f - Z);
        Z = ((V - 1.0f) > 0.0f) ? 1.0f : 0.0f;
        op[(size_t)t * N_UNITS] = Z;
    }
}

extern "C" void kernel_launch(void* const* d_in, const int* in_sizes, int n_in,
                              void* d_out, int out_size)
{
    const float* x = (const float*)d_in[0];   // [8192]
    const float* W = (const float*)d_in[1];   // [8192, 8192]
    float* out = (float*)d_out;               // [256, 8192]

    dim3 grid_mv(N_UNITS / JTILE, KSPLITS);   // (32, 32) = 1024 blocks
    matvec_partial_kernel<<<grid_mv, JTILE>>>(x, W);
    lif_kernel<<<N_UNITS / 256, 256>>>(out);
}